// round 17
// baseline (speedup 1.0000x reference)
#include <cuda_runtime.h>

#define H      1024
#define HH     (H * H)
#define P      (3 * HH)
#define P4     (P / 4)
#define HH4    (HH / 4)
#define NBINS  256
#define NIDX   400000
#define NFLAG  (HH / 32)              // 32768 bitmap words

#define GRID   740                    // exactly 5 blocks/SM * 148 SMs (RF-capacity fill)
#define TPB    256
#define STRIDE (GRID * TPB)           // 189440
#define HBATCH 3                      // 740*256*3 = 568320 >= NIDX

// ---------------- device scratch (no allocation allowed) ----------------
__device__ int                g_hist[6 * NBINS];
__device__ unsigned           g_binD[HH];   // packed bins of ref_masked (b0|b1<<8|b2<<16)
__device__ unsigned           g_binR[HH];   // packed bins of target_masked
__device__ unsigned           g_flag[NFLAG];// "pixel was scattered" bitmap
__device__ float              g_pls[GRID];  // per-block loss partials (slot-per-block)
__device__ unsigned long long g_tick;       // monotonic barrier ticket (never reset)

__device__ __forceinline__ float dn(float x) {
    float v = (x + 1.0f) * 0.5f;
    return fminf(fmaxf(v, 0.0f), 1.0f);
}
__device__ __forceinline__ int binof(float v255) { return min((int)v255, NBINS - 1); }

// Device-wide barrier: monotonic ticket, all blocks hit every barrier, so
// arrivals group into consecutive runs of GRID. Safe across graph replays.
__device__ __forceinline__ void gsync(bool spin) {
    __syncthreads();
    if (threadIdx.x == 0) {
        __threadfence();
        unsigned long long t = atomicAdd(&g_tick, 1ULL) + 1ULL;
        if (spin) {
            unsigned long long tgt = ((t + GRID - 1) / GRID) * (unsigned long long)GRID;
            unsigned long long cur;
            do {
                asm volatile("ld.global.acquire.gpu.u64 %0, [%1];"
                             : "=l"(cur) : "l"(&g_tick));
                if (cur >= tgt) break;
                __nanosleep(64);
            } while (true);
        }
    }
    __syncthreads();
}

__global__ void __launch_bounds__(TPB, 5)
mega_k(const float4* __restrict__ inp, const float4* __restrict__ tgt,
       const float4* __restrict__ ref, const float4* __restrict__ msrc,
       const float4* __restrict__ mtar,
       const int* __restrict__ i0, const int* __restrict__ i1,
       const int* __restrict__ i2, const int* __restrict__ i3,
       float4* __restrict__ out) {
    __shared__ int   sh[6 * NBINS];
    __shared__ float cdf[6][NBINS];
    __shared__ float stab[3][NBINS];
    const int tid = threadIdx.x;
    const int bid = blockIdx.x;
    float* outf = (float*)out;

    // ============ Phase A: elementwise transforms + bin packing ==========
    // (match plane NOT written here; built coalesced in phase C)
    if (bid == 0)
        for (int t = tid; t < 6 * NBINS; t += TPB) g_hist[t] = 0;
    {
        int gtid = bid * TPB + tid;
        if (gtid < NFLAG) g_flag[gtid] = 0u;
    }
    for (int i = bid * TPB + tid; i < HH4; i += STRIDE) {   // pixel-group [0, HH4)
        float4 ms = msrc[i];
        float4 mt = mtar[i];
        float mu[4] = { ms.x != 0.0f ? 1.0f : 0.0f, ms.y != 0.0f ? 1.0f : 0.0f,
                        ms.z != 0.0f ? 1.0f : 0.0f, ms.w != 0.0f ? 1.0f : 0.0f };
        float tu[4] = { mt.x != 0.0f ? 1.0f : 0.0f, mt.y != 0.0f ? 1.0f : 0.0f,
                        mt.z != 0.0f ? 1.0f : 0.0f, mt.w != 0.0f ? 1.0f : 0.0f };
        unsigned pd[4] = {0, 0, 0, 0};
        unsigned pr[4] = {0, 0, 0, 0};
#pragma unroll
        for (int c = 0; c < 3; c++) {
            float4 t = tgt[c * HH4 + i];
            float4 r = ref[c * HH4 + i];
            float4 in = inp[c * HH4 + i];
            float to[4] = {dn(t.x), dn(t.y), dn(t.z), dn(t.w)};
            float ro[4] = {dn(r.x), dn(r.y), dn(r.z), dn(r.w)};
            float io[4] = {fminf(fmaxf(in.x, 0.0f), 1.0f), fminf(fmaxf(in.y, 0.0f), 1.0f),
                           fminf(fmaxf(in.z, 0.0f), 1.0f), fminf(fmaxf(in.w, 0.0f), 1.0f)};
            float4 otm, orm, oim;
            float* potm = (float*)&otm; float* porm = (float*)&orm; float* poim = (float*)&oim;
#pragma unroll
            for (int j = 0; j < 4; j++) {
                float rm = ro[j] * mu[j];
                float tm = to[j] * tu[j];
                potm[j] = tm;
                porm[j] = rm;
                poim[j] = io[j] * mu[j];
                pd[j] |= (unsigned)binof(rm * 255.0f) << (8 * c);
                pr[j] |= (unsigned)binof(tm * 255.0f) << (8 * c);
            }
            out[c * HH4 + i]          = otm;
            out[P4 + c * HH4 + i]     = orm;
            out[2 * P4 + c * HH4 + i] = oim;
        }
        ((uint4*)g_binD)[i] = make_uint4(pd[0], pd[1], pd[2], pd[3]);
        ((uint4*)g_binR)[i] = make_uint4(pr[0], pr[1], pr[2], pr[3]);
    }
    gsync(true);   // barrier 1: bins, planes, zeroed hist/flags visible

    // ============ Phase B: histograms + scattered-pixel flags ============
    for (int t = tid; t < 6 * NBINS; t += TPB) sh[t] = 0;
    __syncthreads();
    {
        int base = bid * TPB + tid;
        int pd[HBATCH];
        unsigned bd[HBATCH], br[HBATCH];
        bool ok[HBATCH];
#pragma unroll
        for (int j = 0; j < HBATCH; j++) {
            int k = base + j * STRIDE;
            ok[j] = (k < NIDX);
            int kk = ok[j] ? k : 0;
            pd[j] = i0[kk] * H + i1[kk];
            bd[j] = g_binD[pd[j]];
            br[j] = g_binR[i2[kk] * H + i3[kk]];
        }
#pragma unroll
        for (int j = 0; j < HBATCH; j++) {
            if (!ok[j]) continue;
            atomicOr(&g_flag[pd[j] >> 5], 1u << (pd[j] & 31));
            atomicAdd(&sh[bd[j] & 255u], 1);
            atomicAdd(&sh[NBINS + ((bd[j] >> 8) & 255u)], 1);
            atomicAdd(&sh[2 * NBINS + ((bd[j] >> 16) & 255u)], 1);
            atomicAdd(&sh[3 * NBINS + (br[j] & 255u)], 1);
            atomicAdd(&sh[4 * NBINS + ((br[j] >> 8) & 255u)], 1);
            atomicAdd(&sh[5 * NBINS + ((br[j] >> 16) & 255u)], 1);
        }
        __syncthreads();
        for (int t = tid; t < 6 * NBINS; t += TPB) {
            int v = sh[t];
            if (v) atomicAdd(&g_hist[t], v);
        }
    }
    gsync(true);   // barrier 2: full histogram + flags visible

    // ============ Phase C: table (per-block) + fused match build + loss ===
    {
        // warp-parallel cumsum: warp w (<6) owns channel w; lane owns 8 bins.
        // Counts are integers <= 400000 < 2^24: any summation order exact in f32.
        int wrp = tid >> 5, lane = tid & 31;
        if (wrp < 6) {
            float v[8];
            float run = 0.0f;
#pragma unroll
            for (int j = 0; j < 8; j++) {
                run += (float)g_hist[wrp * NBINS + lane * 8 + j];
                v[j] = run;
            }
            // inclusive warp scan of per-lane totals
            float pre = run;
#pragma unroll
            for (int off = 1; off < 32; off <<= 1) {
                float t = __shfl_up_sync(0xFFFFFFFFu, pre, off);
                if (lane >= off) pre += t;
            }
            float excl = pre - run;
#pragma unroll
            for (int j = 0; j < 8; j++)
                cdf[wrp][lane * 8 + j] = __fdiv_rn(v[j] + excl, (float)NIDX);
        }
        __syncthreads();

        int b = tid;   // 256 threads
        // transfer table via lower_bound (equivalent to the linear first-match:
        // minimal m in [1,255] with cr[m] >= r; match iff cr[m-1] <= r)
#pragma unroll
        for (int c = 0; c < 3; c++) {
            int tab;
            if (b == NBINS - 1) {
                tab = NBINS - 1;
            } else {
                float r = cdf[c][b];
                const float* cr = cdf[3 + c];
                int lo = 1, hi = NBINS - 1;
                while (lo < hi) {
                    int mid = (lo + hi) >> 1;
                    if (cr[mid] >= r) hi = mid; else lo = mid + 1;
                }
                tab = (cr[lo - 1] <= r) ? lo : b;
            }
            stab[c][b] = __fdiv_rn((float)tab, 255.0f);
        }
        __syncthreads();

        // fused: match = flagged ? stab[bin] : rm ; loss += |im - match|
        const float4* rm4p = (const float4*)(outf + (size_t)P);
        const float4* im4p = (const float4*)(outf + (size_t)2 * P);
        float4*       mt4p = (float4*)(outf + (size_t)3 * P);
        float local = 0.0f;
        for (int i = bid * TPB + tid; i < HH4; i += STRIDE) {   // pixel-group
            uint4 bg = ((uint4*)g_binD)[i];
            unsigned fw = g_flag[i >> 3];
            unsigned bj[4] = {bg.x, bg.y, bg.z, bg.w};
            float4 rmv[3], imv[3];
#pragma unroll
            for (int c = 0; c < 3; c++) {
                rmv[c] = rm4p[c * HH4 + i];
                imv[c] = im4p[c * HH4 + i];
            }
            int bitbase = 4 * (i & 7);
#pragma unroll
            for (int c = 0; c < 3; c++) {
                float4 m4;
                float* pm = (float*)&m4;
                const float* prm = (const float*)&rmv[c];
                const float* pim = (const float*)&imv[c];
#pragma unroll
                for (int j = 0; j < 4; j++) {
                    bool fl = (fw >> (bitbase + j)) & 1u;
                    float m = fl ? stab[c][(bj[j] >> (8 * c)) & 255u] : prm[j];
                    pm[j] = m;
                    local += fabsf(pim[j] - m);
                }
                mt4p[c * HH4 + i] = m4;
            }
        }
        // block reduce
        __shared__ float ws[8];
#pragma unroll
        for (int off = 16; off; off >>= 1) local += __shfl_down_sync(0xFFFFFFFFu, local, off);
        if ((tid & 31) == 0) ws[tid >> 5] = local;
        __syncthreads();
        if (tid < 32) {
            float v = (tid < 8) ? ws[tid] : 0.0f;
#pragma unroll
            for (int off = 4; off; off >>= 1) v += __shfl_down_sync(0xFFFFFFFFu, v, off);
            if (tid == 0) g_pls[bid] = v;
        }
    }
    gsync(bid == 0);   // barrier 3: partials visible; only block 0 spins

    if (bid != 0) return;

    // ============ block 0: final reduction + write loss ==================
    {
        __shared__ double sred[TPB];
        double tot = 0.0;
        for (int i = tid; i < GRID; i += TPB) tot += (double)g_pls[i];
        sred[tid] = tot;
        __syncthreads();
        for (int s = TPB / 2; s; s >>= 1) {
            if (tid < s) sred[tid] += sred[tid + s];
            __syncthreads();
        }
        if (tid == 0) outf[(size_t)4 * P] = (float)(sred[0] / (double)P);
    }
}

// ---------------- launch -------------------------------------------------
extern "C" void kernel_launch(void* const* d_in, const int* in_sizes, int n_in,
                              void* d_out, int out_size) {
    const float* inp  = (const float*)d_in[0];
    const float* tgt  = (const float*)d_in[1];
    const float* ref  = (const float*)d_in[2];
    const float* msrc = (const float*)d_in[3];
    const float* mtar = (const float*)d_in[4];
    // d_in[5] = target_data_eye (unused by reference)
    const int* i0 = (const int*)d_in[6];
    const int* i1 = (const int*)d_in[7];
    const int* i2 = (const int*)d_in[8];
    const int* i3 = (const int*)d_in[9];

    mega_k<<<GRID, TPB>>>((const float4*)inp, (const float4*)tgt,
                          (const float4*)ref, (const float4*)msrc,
                          (const float4*)mtar, i0, i1, i2, i3,
                          (float4*)d_out);
}